// round 9
// baseline (speedup 1.0000x reference)
#include <cuda_runtime.h>
#include <cstdint>
#include <cstddef>

#define BS      64
#define NVAL    25200
#define KCAND   512
#define MAXDET  300
#define CONF_T  0.25f
#define IOU_T   0.45f
#define MAX_WH  7680.0f
#define NBIN    4096
#define CAP     2048

typedef unsigned long long u64;

// ---- static device scratch (no allocation anywhere; zero-initialized) ----
__device__ u64          g_keys[(size_t)BS * NVAL];        // 12.9 MB
__device__ unsigned int g_hist[BS][NBIN];                 // self-resetting
__device__ unsigned int g_cntA[BS];                       // score-block counters
__device__ unsigned int g_cntB[BS];                       // mask-block counters
__device__ float        g_ox1[BS * KCAND], g_oy1[BS * KCAND];
__device__ float        g_ox2[BS * KCAND], g_oy2[BS * KCAND];
__device__ float        g_area[BS * KCAND], g_score[BS * KCAND];
__device__ int          g_cid[BS * KCAND], g_topi[BS * KCAND];
__device__ int          g_nconf[BS];
__device__ u64          g_tmask[(size_t)BS * 8 * KCAND];  // word-major
__device__ u64          g_nzrow[BS][8];

// ===========================================================================
// K_A: score+hist (all blocks) ; last block per image runs exact top-512
//      select + bitonic sort + candidate extraction.
// grid (25, BS) x 1024.  Dynamic smem 26624 B (phases aliased).
// ===========================================================================
extern __shared__ unsigned char smemA[];

__global__ void __launch_bounds__(1024, 1)
kernelA(const float* __restrict__ pred) {
    const int b   = blockIdx.y;
    const int tid = threadIdx.x;

    // score-phase view
    unsigned int* sh = (unsigned int*)smemA;                 // [4096] 16384 B
    // select-phase view (aliases sh; used only after score phase done)
    u64*          buf   = (u64*)smemA;                       // [2048] 16384 B
    u64*          keysS = (u64*)(smemA + 16384);             // [512]   4096 B
    unsigned int* Tarr  = (unsigned int*)(smemA + 20480);    // [1024]  4096 B
    unsigned int* hist  = (unsigned int*)(smemA + 24576);    // [257]

    __shared__ int s_last;
    __shared__ u64 s_pf;
    __shared__ int s_shift, s_done, s_need, s_b12;
    __shared__ unsigned int s_cntS, s_cntB;

    // ---------------- score phase ----------------
    for (int t = tid; t < NBIN; t += 1024) sh[t] = 0u;
    __syncthreads();

    int i = blockIdx.x * 1024 + tid;
    bool act = (i < NVAL);
    unsigned int am = __ballot_sync(0xffffffffu, act);
    if (act) {
        const float4* p = (const float4*)(pred + ((size_t)b * NVAL + i) * 8);
        float4 c = p[1];                           // obj, cls0, cls1, cls2
        float s0 = __fmul_rn(c.x, c.y);
        float s1 = __fmul_rn(c.x, c.z);
        float s2 = __fmul_rn(c.x, c.w);
        float best = s0;
        if (s1 > best) best = s1;
        if (s2 > best) best = s2;
        unsigned int bits = __float_as_uint(best); // scores >= 0 -> monotonic
        g_keys[(size_t)b * NVAL + i] =
            ((u64)bits << 32) | (0xFFFFFFFFu - (unsigned int)i);
        unsigned int bin = bits >> 20;             // 12-bit MSB digit
        unsigned int mm = __match_any_sync(am, bin);
        if ((tid & 31) == (__ffs(mm) - 1))
            atomicAdd(&sh[bin], (unsigned int)__popc(mm));
    }
    __syncthreads();
    for (int t = tid; t < NBIN; t += 1024)
        if (sh[t]) atomicAdd(&g_hist[b][t], sh[t]);
    __syncthreads();

    // ---------------- last-block handoff ----------------
    if (tid == 0) {
        __threadfence();
        unsigned int old = atomicAdd(&g_cntA[b], 1u);
        s_last = (old == 24);
        if (old == 24) { g_cntA[b] = 0u; __threadfence(); }  // reset + acquire
    }
    __syncthreads();
    if (!s_last) return;

    // ---------------- select phase (this block only) ----------------
    const u64* keys = g_keys + (size_t)b * NVAL;

    unsigned int h0, h1, h2, h3;
    {
        int base = tid * 4;
        h0 = g_hist[b][base];     g_hist[b][base]     = 0u;
        h1 = g_hist[b][base + 1]; g_hist[b][base + 1] = 0u;
        h2 = g_hist[b][base + 2]; g_hist[b][base + 2] = 0u;
        h3 = g_hist[b][base + 3]; g_hist[b][base + 3] = 0u;
    }
    unsigned int l3 = h3, l2 = h2 + l3, l1 = h1 + l2, l0 = h0 + l1;
    Tarr[tid] = l0;
    if (tid == 0) { s_done = 0; s_cntS = 0u; s_cntB = 0u; }
    __syncthreads();
    #pragma unroll
    for (int off = 1; off < 1024; off <<= 1) {
        unsigned int v = Tarr[tid] + ((tid + off < 1024) ? Tarr[tid + off] : 0u);
        __syncthreads();
        Tarr[tid] = v;
        __syncthreads();
    }
    {
        unsigned int base = (tid < 1023) ? Tarr[tid + 1] : 0u;
        unsigned int sfx[5];
        sfx[0] = l0 + base; sfx[1] = l1 + base; sfx[2] = l2 + base;
        sfx[3] = l3 + base; sfx[4] = base;
        unsigned int hh[4] = {h0, h1, h2, h3};
        #pragma unroll
        for (int k = 0; k < 4; ++k) {
            if ((int)sfx[k] >= KCAND && (int)sfx[k + 1] < KCAND) {  // unique
                int need_new = KCAND - (int)sfx[k + 1];
                s_b12   = tid * 4 + k;
                s_pf    = (u64)(tid * 4 + k);
                s_shift = 52;
                s_need  = need_new;
                if ((int)hh[k] == need_new) s_done = 1;
            }
        }
    }
    __syncthreads();

    // single global pass: sure-winners -> keysS, threshold bin -> buf
    {
        const unsigned int b12 = (unsigned int)s_b12;
        for (int ii = tid; ii < NVAL; ii += 1024) {
            u64 kk = keys[ii];
            unsigned int d = (unsigned int)(kk >> 52);
            if (d > b12) {
                keysS[atomicAdd(&s_cntS, 1u)] = kk;
            } else if (d == b12) {
                unsigned int p2 = atomicAdd(&s_cntB, 1u);
                if (p2 < CAP) buf[p2] = kk;
            }
        }
    }
    __syncthreads();
    const bool overflow = (s_cntB > CAP);
    const int  nbuf     = overflow ? 0 : (int)s_cntB;
    const unsigned int b12v = (unsigned int)s_b12;

    // deeper radix levels on the smem buffer (or global on overflow)
    for (int lvl = 0; lvl < 7 && !s_done; ++lvl) {
        u64 pf    = s_pf;
        int shift = s_shift;
        int w     = (shift >= 8) ? 8 : shift;
        int nsh   = shift - w;
        if (tid < 257) hist[tid] = 0u;
        __syncthreads();
        if (!overflow) {
            for (int ii = tid; ii < nbuf; ii += 1024) {
                u64 kk = buf[ii];
                if ((kk >> shift) == pf)
                    atomicAdd(&hist[(unsigned int)(kk >> nsh) & ((1u << w) - 1u)], 1u);
            }
        } else {
            for (int ii = tid; ii < NVAL; ii += 1024) {
                u64 kk = keys[ii];
                if ((kk >> shift) == pf)
                    atomicAdd(&hist[(unsigned int)(kk >> nsh) & ((1u << w) - 1u)], 1u);
            }
        }
        __syncthreads();
        #pragma unroll
        for (int off = 1; off < 256; off <<= 1) {
            unsigned int v = 0;
            if (tid < 256)
                v = hist[tid] + ((tid + off < 256) ? hist[tid + off] : 0u);
            __syncthreads();
            if (tid < 256) hist[tid] = v;
            __syncthreads();
        }
        const int need = s_need;      // snapshot in ALL threads (race fix)
        __syncthreads();
        if (tid < 256) {
            unsigned int sfx = hist[tid], sfx1 = hist[tid + 1];
            if ((int)sfx >= need && (int)sfx1 < need) {
                int hbin     = (int)(sfx - sfx1);
                int need_new = need - (int)sfx1;
                s_pf    = (pf << w) | (unsigned int)tid;
                s_shift = nsh;
                s_need  = need_new;
                if (hbin == need_new || nsh == 0) s_done = 1;
            }
        }
        __syncthreads();
    }

    // final compact
    {
        u64 pf    = s_pf;
        int shift = s_shift;
        if (!overflow) {
            for (int ii = tid; ii < nbuf; ii += 1024) {
                u64 kk = buf[ii];
                if ((kk >> shift) >= pf)
                    keysS[atomicAdd(&s_cntS, 1u)] = kk;
            }
        } else {
            for (int ii = tid; ii < NVAL; ii += 1024) {
                u64 kk = keys[ii];
                if (((unsigned int)(kk >> 52) == b12v) && ((kk >> shift) >= pf))
                    keysS[atomicAdd(&s_cntS, 1u)] = kk;
            }
        }
    }
    __syncthreads();

    // bitonic sort descending (512 distinct keys -> deterministic)
    for (int kk = 2; kk <= KCAND; kk <<= 1) {
        for (int j = kk >> 1; j > 0; j >>= 1) {
            if (tid < KCAND) {
                int ixj = tid ^ j;
                if (ixj > tid) {
                    bool dirDesc = ((tid & kk) == 0);
                    u64 a = keysS[tid], c = keysS[ixj];
                    bool sw = dirDesc ? (a < c) : (a > c);
                    if (sw) { keysS[tid] = c; keysS[ixj] = a; }
                }
            }
            __syncthreads();
        }
    }

    // extract candidate data -> global, plus nconf (conf is a sorted prefix)
    if (tid < KCAND) {
        u64 kk = keysS[tid];
        int   idx = (int)(0xFFFFFFFFu - (unsigned int)kk);
        float sc  = __uint_as_float((unsigned int)(kk >> 32));
        const float4* p = (const float4*)(pred + ((size_t)b * NVAL + idx) * 8);
        float4 a = p[0];                 // cx, cy, w, h
        float4 c = p[1];                 // obj, cls0..2
        float s0 = __fmul_rn(c.x, c.y);
        float s1 = __fmul_rn(c.x, c.z);
        float s2 = __fmul_rn(c.x, c.w);
        int cid = 0; float bv = s0;
        if (s1 > bv) { bv = s1; cid = 1; }
        if (s2 > bv) { bv = s2; cid = 2; }
        float hw  = __fmul_rn(a.z, 0.5f), hh = __fmul_rn(a.w, 0.5f);
        float bx1 = __fsub_rn(a.x, hw),  by1 = __fsub_rn(a.y, hh);
        float bx2 = __fadd_rn(a.x, hw),  by2 = __fadd_rn(a.y, hh);
        float off = __fmul_rn((float)cid, MAX_WH);
        float X1 = __fadd_rn(bx1, off), Y1 = __fadd_rn(by1, off);
        float X2 = __fadd_rn(bx2, off), Y2 = __fadd_rn(by2, off);
        int g = b * KCAND + tid;
        g_ox1[g] = X1; g_oy1[g] = Y1; g_ox2[g] = X2; g_oy2[g] = Y2;
        g_area[g]  = __fmul_rn(__fsub_rn(X2, X1), __fsub_rn(Y2, Y1));
        g_score[g] = sc;
        g_cid[g]   = cid;
        g_topi[g]  = idx;

        bool c0 = sc > CONF_T;
        bool c1 = (tid < KCAND - 1)
                ? (__uint_as_float((unsigned int)(keysS[tid + 1] >> 32)) > CONF_T)
                : false;
        if (c0 && !c1) g_nconf[b] = tid + 1;        // unique crossing
        if (tid == 0 && !c0) g_nconf[b] = 0;
    }
}

// ===========================================================================
// K_B: IoU mask (all blocks) ; last block per image runs greedy NMS + pack.
// grid (8, BS) x 512.
// ===========================================================================
__global__ void __launch_bounds__(512)
kernelB(const float* __restrict__ pred, float* __restrict__ out) {
    const int b   = blockIdx.y;
    const int ic  = blockIdx.x;            // row chunk
    const int tid = threadIdx.x;

    __shared__ float sx1[KCAND], sy1[KCAND], sx2[KCAND], sy2[KCAND], sar[KCAND];
    __shared__ u64 s_nz;
    __shared__ int s_last, s_nv;
    __shared__ unsigned int valid32[16];

    {
        int g = b * KCAND + tid;
        sx1[tid] = g_ox1[g]; sy1[tid] = g_oy1[g];
        sx2[tid] = g_ox2[g]; sy2[tid] = g_oy2[g];
        sar[tid] = g_area[g];
    }
    if (tid == 0) s_nz = 0ull;
    __syncthreads();

    // ---------------- mask phase ----------------
    const int w  = tid >> 6;               // j-word 0..7
    const int li = tid & 63;
    const int i  = (ic << 6) + li;         // row
    u64 word = 0ull;
    if (w >= ic) {                         // below-diagonal words are all zero
        float ax1 = sx1[i], ay1 = sy1[i], ax2 = sx2[i], ay2 = sy2[i], aa = sar[i];
        int jbase = w << 6;
        #pragma unroll 4
        for (int bb = 0; bb < 64; ++bb) {
            int j = jbase + bb;
            float ltx = fmaxf(ax1, sx1[j]), lty = fmaxf(ay1, sy1[j]);
            float rbx = fminf(ax2, sx2[j]), rby = fminf(ay2, sy2[j]);
            float iw = fmaxf(__fsub_rn(rbx, ltx), 0.0f);
            float ih = fmaxf(__fsub_rn(rby, lty), 0.0f);
            float inter = __fmul_rn(iw, ih);
            if ((j > i) && (inter > 0.0f)) {   // inter==0 -> iou==0 exactly
                float denom = __fadd_rn(__fsub_rn(__fadd_rn(aa, sar[j]), inter), 1e-7f);
                if (__fdiv_rn(inter, denom) > IOU_T) word |= (1ull << bb);
            }
        }
    }
    g_tmask[((size_t)b * 8 + w) * KCAND + i] = word;   // coalesced
    if (word) atomicOr(&s_nz, 1ull << li);
    __syncthreads();
    if (tid == 0) g_nzrow[b][ic] = s_nz;
    __syncthreads();

    // ---------------- last-block handoff ----------------
    if (tid == 0) {
        __threadfence();
        unsigned int old = atomicAdd(&g_cntB[b], 1u);
        s_last = (old == 7);
        if (old == 7) { g_cntB[b] = 0u; __threadfence(); }   // reset + acquire
    }
    __syncthreads();
    if (!s_last) return;

    // ---------------- final phase (this block only) ----------------
    if (tid == 0) {
        u64 sup[8] = {0,0,0,0,0,0,0,0};
        u64 nz[8];
        #pragma unroll
        for (int q = 0; q < 8; ++q) nz[q] = g_nzrow[b][q];
        #pragma unroll
        for (int ww = 0; ww < 8; ++ww) {
            u64 x = nz[ww] & ~sup[ww];
            while (x) {
                int bb = __ffsll((long long)x) - 1;
                int r = (ww << 6) + bb;
                #pragma unroll
                for (int q = 0; q < 8; ++q)
                    sup[q] |= g_tmask[((size_t)b * 8 + q) * KCAND + r];
                u64 above = (bb == 63) ? 0ull : (~0ull << (bb + 1));
                x = nz[ww] & ~sup[ww] & above;
            }
        }
        int nconf = g_nconf[b];
        int nv = 0;
        #pragma unroll
        for (int ww = 0; ww < 8; ++ww) {
            int lo = nconf - (ww << 6);
            u64 conf = (lo >= 64) ? ~0ull : ((lo <= 0) ? 0ull : ((1ull << lo) - 1ull));
            u64 valid = (~sup[ww]) & conf;
            if (ww == 0) valid |= 1ull;     // index 0: never suppressed, rank 1
            valid32[2*ww]     = (unsigned int)valid;
            valid32[2*ww + 1] = (unsigned int)(valid >> 32);
            nv += __popcll(valid);
        }
        s_nv = nv;
    }
    __syncthreads();

    if (tid < MAXDET) {
        int nv = s_nv;
        bool isv = tid < nv;
        int r = isv ? tid : tid - nv;
        int k = -1;
        #pragma unroll
        for (int wi = 0; wi < 16; ++wi) {
            unsigned wv = valid32[wi];
            if (!isv) wv = ~wv;
            int c = __popc(wv);
            if (k < 0) {
                if (r < c) k = wi * 32 + __fns(wv, 0, r + 1);
                else       r -= c;
            }
        }
        int g  = b * KCAND + k;
        int gi = g_topi[g];
        float b0 = 0.f, b1 = 0.f, b2 = 0.f, b3 = 0.f, sc = 0.f;
        if (isv) {
            const float4* p = (const float4*)(pred + ((size_t)b * NVAL + gi) * 8);
            float4 a = p[0];
            float hw = __fmul_rn(a.z, 0.5f), hh = __fmul_rn(a.w, 0.5f);
            b0 = __fsub_rn(a.x, hw); b1 = __fsub_rn(a.y, hh);
            b2 = __fadd_rn(a.x, hw); b3 = __fadd_rn(a.y, hh);
            sc = g_score[g];
        }
        const size_t scoresOff = (size_t)BS * MAXDET * 4;
        const size_t clsOff    = scoresOff + (size_t)BS * MAXDET;
        const size_t idsOff    = clsOff    + (size_t)BS * MAXDET;
        const size_t valOff    = idsOff    + (size_t)BS * MAXDET;
        size_t rr = (size_t)b * MAXDET + tid;
        out[rr * 4 + 0] = b0;
        out[rr * 4 + 1] = b1;
        out[rr * 4 + 2] = b2;
        out[rr * 4 + 3] = b3;
        out[scoresOff + rr] = sc;
        out[clsOff + rr] = (float)g_cid[g];    // NOT zeroed for pads (ref semantics)
        out[idsOff + rr] = (float)(gi / 3);    // NOT zeroed for pads (ref semantics)
        out[valOff + rr] = isv ? 1.0f : 0.0f;
    }
}

// ---------------------------------------------------------------------------
extern "C" void kernel_launch(void* const* d_in, const int* in_sizes, int n_in,
                              void* d_out, int out_size) {
    (void)in_sizes; (void)n_in; (void)out_size;
    const float* pred = (const float*)d_in[0];
    float* out = (float*)d_out;

    cudaFuncSetAttribute(kernelA,
                         cudaFuncAttributeMaxDynamicSharedMemorySize, 26624);
    kernelA<<<dim3(25, BS), 1024, 26624>>>(pred);
    kernelB<<<dim3(8, BS), 512>>>(pred, out);
}

// round 14
// speedup vs baseline: 1.4229x; 1.4229x over previous
#include <cuda_runtime.h>
#include <cstdint>
#include <cstddef>

#define BS      64
#define NVAL    25200
#define KCAND   512
#define MAXDET  300
#define CONF_T  0.25f
#define IOU_T   0.45f
#define MAX_WH  7680.0f
#define NBIN    4096
#define CAP     6144

typedef unsigned long long u64;

// ---- static device scratch (no allocation anywhere; zero-initialized) ----
__device__ u64          g_keys[(size_t)BS * NVAL];        // 12.9 MB
__device__ unsigned int g_hist[BS][NBIN];                 // self-resetting

// ---------------------------------------------------------------------------
// K1: scores -> 64-bit sortable keys + per-image 4096-bin MSB histogram.
// ---------------------------------------------------------------------------
__global__ void score_kernel(const float* __restrict__ pred) {
    const int b = blockIdx.y;
    const int i = blockIdx.x * 1024 + threadIdx.x;
    __shared__ unsigned int sh[NBIN];
    for (int t = threadIdx.x; t < NBIN; t += 1024) sh[t] = 0u;
    __syncthreads();

    bool act = (i < NVAL);
    unsigned int am = __ballot_sync(0xffffffffu, act);
    if (act) {
        const float4* p = (const float4*)(pred + ((size_t)b * NVAL + i) * 8);
        float4 c = p[1];                           // obj, cls0, cls1, cls2
        float s0 = __fmul_rn(c.x, c.y);
        float s1 = __fmul_rn(c.x, c.z);
        float s2 = __fmul_rn(c.x, c.w);
        float best = s0;
        if (s1 > best) best = s1;
        if (s2 > best) best = s2;
        unsigned int bits = __float_as_uint(best); // scores >= 0 -> monotonic
        g_keys[(size_t)b * NVAL + i] =
            ((u64)bits << 32) | (0xFFFFFFFFu - (unsigned int)i);
        unsigned int bin = bits >> 20;             // 12-bit MSB digit
        unsigned int mm = __match_any_sync(am, bin);
        if ((threadIdx.x & 31) == (__ffs(mm) - 1))
            atomicAdd(&sh[bin], (unsigned int)__popc(mm));
    }
    __syncthreads();
    for (int t = threadIdx.x; t < NBIN; t += 1024)
        if (sh[t]) atomicAdd(&g_hist[b][t], sh[t]);
}

// ---------------------------------------------------------------------------
// K2 (per-image, fused): rank-sort top-512 select + IoU mask in smem +
//     sparse greedy NMS + pack. One block / image, 1024 threads.
// Dynamic smem 102400 B:
//   buf   [CAP]  u64   @ 0        49152
//   tm    [8*512]u64   @ 49152    32768   (word-major mask)
//   keysS [512]  u64   @ 81920     4096
//   sx1,sy1,sx2,sy2,sar,scoreS : 6*512 f32 @ 86016   12288
//   cidS,topiS : 2*512 i32       @ 98304    4096
// ---------------------------------------------------------------------------
extern __shared__ unsigned char smdyn[];

__global__ void __launch_bounds__(1024, 1)
perimage_kernel(const float* __restrict__ pred, float* __restrict__ out) {
    const int b   = blockIdx.x;
    const int tid = threadIdx.x;
    const int lane = tid & 31, wrp = tid >> 5;

    u64*   buf    = (u64*)(smdyn);
    u64*   tm     = (u64*)(smdyn + 49152);
    u64*   keysS  = (u64*)(smdyn + 81920);
    float* sx1    = (float*)(smdyn + 86016);
    float* sy1    = sx1 + KCAND;
    float* sx2    = sy1 + KCAND;
    float* sy2    = sx2 + KCAND;
    float* sar    = sy2 + KCAND;
    float* scoreS = sar + KCAND;
    int*   cidS   = (int*)(smdyn + 98304);
    int*   topiS  = cidS + KCAND;

    __shared__ unsigned int warpTot[32];
    __shared__ unsigned int hist[257];
    __shared__ u64 s_pf;
    __shared__ int s_b12, s_need, s_shift, s_done, s_nv, s_nconf;
    __shared__ unsigned int s_cnt;
    __shared__ unsigned int nz32[16], valid32[16];

    const u64* keys = g_keys + (size_t)b * NVAL;

    // ========== 1. threshold digit from pre-hist (2 barriers) ==========
    unsigned int h0, h1, h2, h3;
    {
        int base = tid * 4;
        h0 = g_hist[b][base];     g_hist[b][base]     = 0u;
        h1 = g_hist[b][base + 1]; g_hist[b][base + 1] = 0u;
        h2 = g_hist[b][base + 2]; g_hist[b][base + 2] = 0u;
        h3 = g_hist[b][base + 3]; g_hist[b][base + 3] = 0u;
    }
    unsigned int s = h0 + h1 + h2 + h3;
    unsigned int v = s;
    #pragma unroll
    for (int off = 1; off < 32; off <<= 1) {
        unsigned int o = __shfl_down_sync(0xffffffffu, v, off);
        if (lane + off < 32) v += o;
    }
    if (lane == 0) warpTot[wrp] = v;          // warp total
    if (tid == 0) s_cnt = 0u;
    __syncthreads();
    if (tid < 32) {
        unsigned int wv = warpTot[tid];
        unsigned int x = wv;
        #pragma unroll
        for (int off = 1; off < 32; off <<= 1) {
            unsigned int o = __shfl_down_sync(0xffffffffu, x, off);
            if (tid + off < 32) x += o;
        }
        warpTot[tid] = x - wv;                // sum over warps > tid
    }
    __syncthreads();
    {
        unsigned int after = v + warpTot[wrp] - s;   // sum over threads > tid
        unsigned int sfx4 = after;
        unsigned int sfx3 = sfx4 + h3;
        unsigned int sfx2 = sfx3 + h2;
        unsigned int sfx1 = sfx2 + h1;
        unsigned int sfx0 = sfx1 + h0;
        unsigned int sfx[5] = {sfx0, sfx1, sfx2, sfx3, sfx4};
        unsigned int hh[4] = {h0, h1, h2, h3};
        #pragma unroll
        for (int k = 0; k < 4; ++k) {
            if ((int)sfx[k] >= KCAND && (int)sfx[k + 1] < KCAND) {  // unique
                s_b12  = tid * 4 + k;
                s_need = KCAND - (int)sfx[k + 1];
                s_done = ((int)hh[k] == KCAND - (int)sfx[k + 1]);
                (void)s_done;
            }
        }
    }
    __syncthreads();

    // ========== 2. one global pass: digit >= b12 -> buf ==========
    const unsigned int b12 = (unsigned int)s_b12;
    for (int ii = tid; ii < NVAL; ii += 1024) {
        u64 kk = keys[ii];
        if ((unsigned int)(kk >> 52) >= b12) {
            unsigned int p = atomicAdd(&s_cnt, 1u);
            if (p < CAP) buf[p] = kk;
        }
    }
    __syncthreads();
    const int n = (int)s_cnt;

    if (n <= CAP) {
        // ===== 3a. rank-sort: rank = #greater keys; scatter rank<512 =====
        for (int t = tid; t < n; t += 1024) {
            u64 me = buf[t];
            int rank = 0;
            for (int j = 0; j < n; ++j) rank += (buf[j] > me);
            if (rank < KCAND) keysS[rank] = me;
        }
    } else {
        // ===== 3b. fallback: global radix refinement (rare) =====
        if (tid == 0) {
            s_pf = (u64)b12; s_shift = 52;
            s_done = 0;
        }
        __syncthreads();
        for (int lvl = 0; lvl < 8 && !s_done; ++lvl) {
            u64 pf    = s_pf;
            int shift = s_shift;
            int w     = (shift >= 8) ? 8 : shift;
            int nsh   = shift - w;
            if (tid < 257) hist[tid] = 0u;
            __syncthreads();
            for (int ii = tid; ii < NVAL; ii += 1024) {
                u64 kk = keys[ii];
                if ((kk >> shift) == pf)
                    atomicAdd(&hist[(unsigned int)(kk >> nsh) & ((1u << w) - 1u)], 1u);
            }
            __syncthreads();
            #pragma unroll
            for (int off = 1; off < 256; off <<= 1) {
                unsigned int vv = 0;
                if (tid < 256)
                    vv = hist[tid] + ((tid + off < 256) ? hist[tid + off] : 0u);
                __syncthreads();
                if (tid < 256) hist[tid] = vv;
                __syncthreads();
            }
            const int need = s_need;          // snapshot in ALL threads
            __syncthreads();
            if (tid < 256) {
                unsigned int sfx = hist[tid], sfx1 = hist[tid + 1];
                if ((int)sfx >= need && (int)sfx1 < need) {
                    int hbin     = (int)(sfx - sfx1);
                    int need_new = need - (int)sfx1;
                    s_pf    = (pf << w) | (unsigned int)tid;
                    s_shift = nsh;
                    s_need  = need_new;
                    if (hbin == need_new || nsh == 0) s_done = 1;
                }
            }
            __syncthreads();
        }
        if (tid == 0) s_cnt = 0u;
        __syncthreads();
        {
            u64 pf    = s_pf;
            int shift = s_shift;
            for (int ii = tid; ii < NVAL; ii += 1024) {
                u64 kk = keys[ii];
                unsigned int d = (unsigned int)(kk >> 52);
                if (d > b12 || (d == b12 && (kk >> shift) >= pf))
                    buf[atomicAdd(&s_cnt, 1u)] = kk;   // exactly 512
            }
        }
        __syncthreads();
        if (tid < KCAND) {
            u64 me = buf[tid];
            int rank = 0;
            for (int j = 0; j < KCAND; ++j) rank += (buf[j] > me);
            keysS[rank] = me;
        }
    }
    __syncthreads();

    // ========== 4. extract candidates into smem + nconf prefix ==========
    if (tid < KCAND) {
        u64 kk = keysS[tid];
        int   idx = (int)(0xFFFFFFFFu - (unsigned int)kk);
        float sc  = __uint_as_float((unsigned int)(kk >> 32));
        const float4* p = (const float4*)(pred + ((size_t)b * NVAL + idx) * 8);
        float4 a = p[0];                 // cx, cy, w, h
        float4 c = p[1];                 // obj, cls0..2
        float s0 = __fmul_rn(c.x, c.y);
        float s1 = __fmul_rn(c.x, c.z);
        float s2 = __fmul_rn(c.x, c.w);
        int cid = 0; float bv = s0;
        if (s1 > bv) { bv = s1; cid = 1; }
        if (s2 > bv) { bv = s2; cid = 2; }
        float hw  = __fmul_rn(a.z, 0.5f), hh = __fmul_rn(a.w, 0.5f);
        float bx1 = __fsub_rn(a.x, hw),  by1 = __fsub_rn(a.y, hh);
        float bx2 = __fadd_rn(a.x, hw),  by2 = __fadd_rn(a.y, hh);
        float off = __fmul_rn((float)cid, MAX_WH);
        float X1 = __fadd_rn(bx1, off), Y1 = __fadd_rn(by1, off);
        float X2 = __fadd_rn(bx2, off), Y2 = __fadd_rn(by2, off);
        sx1[tid] = X1; sy1[tid] = Y1; sx2[tid] = X2; sy2[tid] = Y2;
        sar[tid]    = __fmul_rn(__fsub_rn(X2, X1), __fsub_rn(Y2, Y1));
        scoreS[tid] = sc;
        cidS[tid]   = cid;
        topiS[tid]  = idx;

        bool c0 = sc > CONF_T;
        bool c1 = (tid < KCAND - 1)
                ? (__uint_as_float((unsigned int)(keysS[tid + 1] >> 32)) > CONF_T)
                : false;
        if (c0 && !c1) s_nconf = tid + 1;          // unique crossing
        if (tid == 0 && !c0) s_nconf = 0;
    }
    __syncthreads();

    // ========== 5. IoU mask in smem (word-major) ==========
    {
        const int i   = tid & (KCAND - 1);
        const int wlo = (tid >> 9) << 2;
        const int ic  = i >> 6;
        float ax1 = sx1[i], ay1 = sy1[i], ax2 = sx2[i], ay2 = sy2[i], aa = sar[i];
        #pragma unroll
        for (int dw = 0; dw < 4; ++dw) {
            int w = wlo + dw;
            u64 word = 0ull;
            if (w >= ic) {                         // below-diagonal words all zero
                int jbase = w << 6;
                #pragma unroll 4
                for (int bb = 0; bb < 64; ++bb) {
                    int j = jbase + bb;
                    float ltx = fmaxf(ax1, sx1[j]), lty = fmaxf(ay1, sy1[j]);
                    float rbx = fminf(ax2, sx2[j]), rby = fminf(ay2, sy2[j]);
                    float iw = fmaxf(__fsub_rn(rbx, ltx), 0.0f);
                    float ih = fmaxf(__fsub_rn(rby, lty), 0.0f);
                    float inter = __fmul_rn(iw, ih);
                    if ((j > i) && (inter > 0.0f)) {   // inter==0 -> iou==0 exactly
                        float denom = __fadd_rn(__fsub_rn(__fadd_rn(aa, sar[j]), inter), 1e-7f);
                        if (__fdiv_rn(inter, denom) > IOU_T) word |= (1ull << bb);
                    }
                }
            }
            tm[w * KCAND + i] = word;
        }
    }
    __syncthreads();

    // ========== 6. nonzero-row bitmap ==========
    if (tid < KCAND) {
        u64 o = tm[tid]            | tm[KCAND     + tid] |
                tm[2*KCAND + tid]  | tm[3*KCAND   + tid] |
                tm[4*KCAND + tid]  | tm[5*KCAND   + tid] |
                tm[6*KCAND + tid]  | tm[7*KCAND   + tid];
        unsigned bnz = __ballot_sync(0xffffffffu, o != 0ull);
        if ((tid & 31) == 0) nz32[tid >> 5] = bnz;
    }
    __syncthreads();

    // ========== 7. sparse serial greedy (smem latency) ==========
    if (tid == 0) {
        u64 sup[8] = {0,0,0,0,0,0,0,0};
        u64 nz[8];
        #pragma unroll
        for (int q = 0; q < 8; ++q)
            nz[q] = (u64)nz32[2*q] | ((u64)nz32[2*q + 1] << 32);
        #pragma unroll
        for (int w = 0; w < 8; ++w) {
            u64 x = nz[w] & ~sup[w];
            while (x) {
                int bb = __ffsll((long long)x) - 1;
                int i = (w << 6) + bb;
                #pragma unroll
                for (int q = 0; q < 8; ++q) sup[q] |= tm[q * KCAND + i];
                u64 above = (bb == 63) ? 0ull : (~0ull << (bb + 1));
                x = nz[w] & ~sup[w] & above;
            }
        }
        int nconf = s_nconf;
        int nv = 0;
        #pragma unroll
        for (int w = 0; w < 8; ++w) {
            int lo = nconf - (w << 6);
            u64 conf = (lo >= 64) ? ~0ull : ((lo <= 0) ? 0ull : ((1ull << lo) - 1ull));
            u64 valid = (~sup[w]) & conf;
            if (w == 0) valid |= 1ull;     // index 0: never suppressed, rank 1
            valid32[2*w]     = (unsigned int)valid;
            valid32[2*w + 1] = (unsigned int)(valid >> 32);
            nv += __popcll(valid);
        }
        s_nv = nv;
    }
    __syncthreads();

    // ========== 8. parallel pack (valid asc, then invalid asc) ==========
    if (tid < MAXDET) {
        int nv = s_nv;
        bool isv = tid < nv;
        int r = isv ? tid : tid - nv;
        int k = -1;
        #pragma unroll
        for (int wi = 0; wi < 16; ++wi) {
            unsigned wv = valid32[wi];
            if (!isv) wv = ~wv;
            int c = __popc(wv);
            if (k < 0) {
                if (r < c) k = wi * 32 + __fns(wv, 0, r + 1);
                else       r -= c;
            }
        }
        int gi = topiS[k];
        float b0 = 0.f, b1 = 0.f, b2 = 0.f, b3 = 0.f, sc = 0.f;
        if (isv) {
            const float4* p = (const float4*)(pred + ((size_t)b * NVAL + gi) * 8);
            float4 a = p[0];
            float hw = __fmul_rn(a.z, 0.5f), hh = __fmul_rn(a.w, 0.5f);
            b0 = __fsub_rn(a.x, hw); b1 = __fsub_rn(a.y, hh);
            b2 = __fadd_rn(a.x, hw); b3 = __fadd_rn(a.y, hh);
            sc = scoreS[k];
        }
        const size_t scoresOff = (size_t)BS * MAXDET * 4;
        const size_t clsOff    = scoresOff + (size_t)BS * MAXDET;
        const size_t idsOff    = clsOff    + (size_t)BS * MAXDET;
        const size_t valOff    = idsOff    + (size_t)BS * MAXDET;
        size_t rr = (size_t)b * MAXDET + tid;
        out[rr * 4 + 0] = b0;
        out[rr * 4 + 1] = b1;
        out[rr * 4 + 2] = b2;
        out[rr * 4 + 3] = b3;
        out[scoresOff + rr] = sc;
        out[clsOff + rr] = (float)cidS[k];     // NOT zeroed for pads (ref semantics)
        out[idsOff + rr] = (float)(gi / 3);    // NOT zeroed for pads (ref semantics)
        out[valOff + rr] = isv ? 1.0f : 0.0f;
    }
}

// ---------------------------------------------------------------------------
extern "C" void kernel_launch(void* const* d_in, const int* in_sizes, int n_in,
                              void* d_out, int out_size) {
    (void)in_sizes; (void)n_in; (void)out_size;
    const float* pred = (const float*)d_in[0];
    float* out = (float*)d_out;

    score_kernel<<<dim3(25, BS), 1024>>>(pred);
    cudaFuncSetAttribute(perimage_kernel,
                         cudaFuncAttributeMaxDynamicSharedMemorySize, 102400);
    perimage_kernel<<<BS, 1024, 102400>>>(pred, out);
}

// round 15
// speedup vs baseline: 1.5548x; 1.0927x over previous
#include <cuda_runtime.h>
#include <cstdint>
#include <cstddef>

#define BS      64
#define NVAL    25200
#define KCAND   512
#define MAXDET  300
#define CONF_T  0.25f
#define IOU_T   0.45f
#define MAX_WH  7680.0f
#define NBIN    4096
#define CAP     6144

typedef unsigned long long u64;

// ---- static device scratch (no allocation anywhere; zero-initialized) ----
__device__ u64          g_keys[(size_t)BS * NVAL];        // 12.9 MB
__device__ unsigned int g_hist[BS][NBIN];                 // self-resetting

// ---------------------------------------------------------------------------
// K1: scores -> 64-bit sortable keys + per-image 4096-bin MSB histogram.
// ---------------------------------------------------------------------------
__global__ void score_kernel(const float* __restrict__ pred) {
    const int b = blockIdx.y;
    const int i = blockIdx.x * 1024 + threadIdx.x;
    __shared__ unsigned int sh[NBIN];
    for (int t = threadIdx.x; t < NBIN; t += 1024) sh[t] = 0u;
    __syncthreads();

    bool act = (i < NVAL);
    unsigned int am = __ballot_sync(0xffffffffu, act);
    if (act) {
        const float4* p = (const float4*)(pred + ((size_t)b * NVAL + i) * 8);
        float4 c = p[1];                           // obj, cls0, cls1, cls2
        float s0 = __fmul_rn(c.x, c.y);
        float s1 = __fmul_rn(c.x, c.z);
        float s2 = __fmul_rn(c.x, c.w);
        float best = s0;
        if (s1 > best) best = s1;
        if (s2 > best) best = s2;
        unsigned int bits = __float_as_uint(best); // scores >= 0 -> monotonic
        g_keys[(size_t)b * NVAL + i] =
            ((u64)bits << 32) | (0xFFFFFFFFu - (unsigned int)i);
        unsigned int bin = bits >> 20;             // 12-bit MSB digit
        unsigned int mm = __match_any_sync(am, bin);
        if ((threadIdx.x & 31) == (__ffs(mm) - 1))
            atomicAdd(&sh[bin], (unsigned int)__popc(mm));
    }
    __syncthreads();
    for (int t = threadIdx.x; t < NBIN; t += 1024)
        if (sh[t]) atomicAdd(&g_hist[b][t], sh[t]);
}

// ---------------------------------------------------------------------------
// K2 (per-image, fused): rank-sort top-512 select + class-partitioned IoU
//     mask in smem + sparse greedy NMS + pack. 1 block/image, 1024 threads.
// Dynamic smem 106496 B:
//   buf[CAP]u64 @0 (49152) | tm[8*512]u64 @49152 (32768) | keysS @81920 (4096)
//   sbox f4[512] @86016 (8192) | sar @94208 | scoreS @96256 | cidS @98304
//   topiS @100352 | memberL @102400 | myrank @104448  (each 2048)
// ---------------------------------------------------------------------------
extern __shared__ unsigned char smdyn[];

__global__ void __launch_bounds__(1024, 1)
perimage_kernel(const float* __restrict__ pred, float* __restrict__ out) {
    const int b   = blockIdx.x;
    const int tid = threadIdx.x;
    const int lane = tid & 31, wrp = tid >> 5;

    u64*    buf    = (u64*)(smdyn);
    u64*    tm     = (u64*)(smdyn + 49152);
    u64*    keysS  = (u64*)(smdyn + 81920);
    float4* sbox   = (float4*)(smdyn + 86016);
    float*  sar    = (float*)(smdyn + 94208);
    float*  scoreS = (float*)(smdyn + 96256);
    int*    cidS   = (int*)(smdyn + 98304);
    int*    topiS  = (int*)(smdyn + 100352);
    int*    memberL= (int*)(smdyn + 102400);
    int*    myrank = (int*)(smdyn + 104448);

    __shared__ unsigned int warpTot[32];
    __shared__ int warpPfx[32];
    __shared__ int s_classBase[4];
    __shared__ unsigned int hist[257];
    __shared__ u64 s_pf;
    __shared__ int s_b12, s_need, s_shift, s_done, s_nv, s_nconf;
    __shared__ unsigned int s_cnt;
    __shared__ unsigned int nz32[16], valid32[16];

    const u64* keys = g_keys + (size_t)b * NVAL;

    // ========== 1. threshold digit from pre-hist (2 barriers) ==========
    unsigned int h0, h1, h2, h3;
    {
        int base = tid * 4;
        h0 = g_hist[b][base];     g_hist[b][base]     = 0u;
        h1 = g_hist[b][base + 1]; g_hist[b][base + 1] = 0u;
        h2 = g_hist[b][base + 2]; g_hist[b][base + 2] = 0u;
        h3 = g_hist[b][base + 3]; g_hist[b][base + 3] = 0u;
    }
    unsigned int s = h0 + h1 + h2 + h3;
    unsigned int v = s;
    #pragma unroll
    for (int off = 1; off < 32; off <<= 1) {
        unsigned int o = __shfl_down_sync(0xffffffffu, v, off);
        if (lane + off < 32) v += o;
    }
    if (lane == 0) warpTot[wrp] = v;
    if (tid == 0) s_cnt = 0u;
    __syncthreads();
    if (tid < 32) {
        unsigned int wv = warpTot[tid];
        unsigned int x = wv;
        #pragma unroll
        for (int off = 1; off < 32; off <<= 1) {
            unsigned int o = __shfl_down_sync(0xffffffffu, x, off);
            if (tid + off < 32) x += o;
        }
        warpTot[tid] = x - wv;                // sum over warps > tid
    }
    __syncthreads();
    {
        unsigned int after = v + warpTot[wrp] - s;   // sum over threads > tid
        unsigned int sfx4 = after;
        unsigned int sfx3 = sfx4 + h3;
        unsigned int sfx2 = sfx3 + h2;
        unsigned int sfx1 = sfx2 + h1;
        unsigned int sfx0 = sfx1 + h0;
        unsigned int sfx[5] = {sfx0, sfx1, sfx2, sfx3, sfx4};
        unsigned int hh[4] = {h0, h1, h2, h3};
        #pragma unroll
        for (int k = 0; k < 4; ++k) {
            if ((int)sfx[k] >= KCAND && (int)sfx[k + 1] < KCAND) {  // unique
                s_b12  = tid * 4 + k;
                s_need = KCAND - (int)sfx[k + 1];
                s_done = ((int)hh[k] == KCAND - (int)sfx[k + 1]);
                (void)s_done;
            }
        }
    }
    __syncthreads();

    // ========== 2. one global pass (vectorized): digit >= b12 -> buf ==========
    const unsigned int b12 = (unsigned int)s_b12;
    {
        const ulonglong2* keys2 = (const ulonglong2*)keys;   // NVAL even, 16B-aligned
        for (int ii = tid; ii < NVAL / 2; ii += 1024) {
            ulonglong2 kv = keys2[ii];
            if ((unsigned int)(kv.x >> 52) >= b12) {
                unsigned int p = atomicAdd(&s_cnt, 1u);
                if (p < CAP) buf[p] = kv.x;
            }
            if ((unsigned int)(kv.y >> 52) >= b12) {
                unsigned int p = atomicAdd(&s_cnt, 1u);
                if (p < CAP) buf[p] = kv.y;
            }
        }
    }
    __syncthreads();
    const int n = (int)s_cnt;

    if (n <= CAP) {
        // ===== 3a. rank-sort: rank = #greater keys; scatter rank<512 =====
        for (int t = tid; t < n; t += 1024) {
            u64 me = buf[t];
            int rank = 0;
            #pragma unroll 4
            for (int j = 0; j < n; ++j) rank += (buf[j] > me);
            if (rank < KCAND) keysS[rank] = me;
        }
    } else {
        // ===== 3b. fallback: global radix refinement (rare, exact) =====
        if (tid == 0) { s_pf = (u64)b12; s_shift = 52; s_done = 0; }
        __syncthreads();
        for (int lvl = 0; lvl < 8 && !s_done; ++lvl) {
            u64 pf    = s_pf;
            int shift = s_shift;
            int w     = (shift >= 8) ? 8 : shift;
            int nsh   = shift - w;
            if (tid < 257) hist[tid] = 0u;
            __syncthreads();
            for (int ii = tid; ii < NVAL; ii += 1024) {
                u64 kk = keys[ii];
                if ((kk >> shift) == pf)
                    atomicAdd(&hist[(unsigned int)(kk >> nsh) & ((1u << w) - 1u)], 1u);
            }
            __syncthreads();
            #pragma unroll
            for (int off = 1; off < 256; off <<= 1) {
                unsigned int vv = 0;
                if (tid < 256)
                    vv = hist[tid] + ((tid + off < 256) ? hist[tid + off] : 0u);
                __syncthreads();
                if (tid < 256) hist[tid] = vv;
                __syncthreads();
            }
            const int need = s_need;          // snapshot in ALL threads
            __syncthreads();
            if (tid < 256) {
                unsigned int sfx = hist[tid], sfx1 = hist[tid + 1];
                if ((int)sfx >= need && (int)sfx1 < need) {
                    int hbin     = (int)(sfx - sfx1);
                    int need_new = need - (int)sfx1;
                    s_pf    = (pf << w) | (unsigned int)tid;
                    s_shift = nsh;
                    s_need  = need_new;
                    if (hbin == need_new || nsh == 0) s_done = 1;
                }
            }
            __syncthreads();
        }
        if (tid == 0) s_cnt = 0u;
        __syncthreads();
        {
            u64 pf    = s_pf;
            int shift = s_shift;
            for (int ii = tid; ii < NVAL; ii += 1024) {
                u64 kk = keys[ii];
                unsigned int d = (unsigned int)(kk >> 52);
                if (d > b12 || (d == b12 && (kk >> shift) >= pf))
                    buf[atomicAdd(&s_cnt, 1u)] = kk;   // exactly 512
            }
        }
        __syncthreads();
        if (tid < KCAND) {
            u64 me = buf[tid];
            int rank = 0;
            #pragma unroll 4
            for (int j = 0; j < KCAND; ++j) rank += (buf[j] > me);
            keysS[rank] = me;
        }
    }
    __syncthreads();

    // ========== 4. extract candidates into smem + nconf prefix ==========
    if (tid < KCAND) {
        u64 kk = keysS[tid];
        int   idx = (int)(0xFFFFFFFFu - (unsigned int)kk);
        float sc  = __uint_as_float((unsigned int)(kk >> 32));
        const float4* p = (const float4*)(pred + ((size_t)b * NVAL + idx) * 8);
        float4 a = p[0];                 // cx, cy, w, h
        float4 c = p[1];                 // obj, cls0..2
        float s0 = __fmul_rn(c.x, c.y);
        float s1 = __fmul_rn(c.x, c.z);
        float s2 = __fmul_rn(c.x, c.w);
        int cid = 0; float bv = s0;
        if (s1 > bv) { bv = s1; cid = 1; }
        if (s2 > bv) { bv = s2; cid = 2; }
        float hw  = __fmul_rn(a.z, 0.5f), hh = __fmul_rn(a.w, 0.5f);
        float bx1 = __fsub_rn(a.x, hw),  by1 = __fsub_rn(a.y, hh);
        float bx2 = __fadd_rn(a.x, hw),  by2 = __fadd_rn(a.y, hh);
        float off = __fmul_rn((float)cid, MAX_WH);
        float X1 = __fadd_rn(bx1, off), Y1 = __fadd_rn(by1, off);
        float X2 = __fadd_rn(bx2, off), Y2 = __fadd_rn(by2, off);
        sbox[tid]   = make_float4(X1, Y1, X2, Y2);
        sar[tid]    = __fmul_rn(__fsub_rn(X2, X1), __fsub_rn(Y2, Y1));
        scoreS[tid] = sc;
        cidS[tid]   = cid;
        topiS[tid]  = idx;

        bool c0 = sc > CONF_T;
        bool c1 = (tid < KCAND - 1)
                ? (__uint_as_float((unsigned int)(keysS[tid + 1] >> 32)) > CONF_T)
                : false;
        if (c0 && !c1) s_nconf = tid + 1;          // unique crossing
        if (tid == 0 && !c0) s_nconf = 0;
    }
    __syncthreads();

    // ========== 4b. per-class member lists (order-preserving) ==========
    if (tid == 0) s_classBase[0] = 0;
    {
        int myc = (tid < KCAND) ? cidS[tid] : -1;
        for (int c = 0; c < 3; ++c) {
            bool pred2 = (myc == c);
            unsigned int m = __ballot_sync(0xffffffffu, pred2);
            int lanePfx = __popc(m & ((1u << lane) - 1u));
            if (lane == 0) warpTot[wrp] = __popc(m);
            __syncthreads();
            if (tid == 0) {
                int run = 0;
                for (int w2 = 0; w2 < 32; ++w2) { warpPfx[w2] = run; run += (int)warpTot[w2]; }
                s_classBase[c + 1] = s_classBase[c] + run;
            }
            __syncthreads();
            if (pred2) {
                int pos = s_classBase[c] + warpPfx[wrp] + lanePfx;
                memberL[pos] = tid;
                myrank[tid]  = pos;
            }
            __syncthreads();
        }
    }

    // ========== 5. class-partitioned IoU mask (smem, word-major) ==========
    for (int t = tid; t < KCAND * 8; t += 1024) tm[t] = 0ull;   // zero mask
    __syncthreads();
    {
        const int half = tid >> 9;
        const int i    = tid & (KCAND - 1);
        const int c    = cidS[i];
        const int mp   = myrank[i];
        const int end  = s_classBase[c + 1];
        float4 bi = sbox[i];
        float  aa = sar[i];
        for (int mj = mp + 1 + half; mj < end; mj += 2) {
            int j = memberL[mj];                      // j > i (ascending in class)
            float4 bj = sbox[j];
            float ltx = fmaxf(bi.x, bj.x), lty = fmaxf(bi.y, bj.y);
            float rbx = fminf(bi.z, bj.z), rby = fminf(bi.w, bj.w);
            float iw = fmaxf(__fsub_rn(rbx, ltx), 0.0f);
            float ih = fmaxf(__fsub_rn(rby, lty), 0.0f);
            float inter = __fmul_rn(iw, ih);
            if (inter > 0.0f) {                       // inter==0 -> iou==0 exactly
                float denom = __fadd_rn(__fsub_rn(__fadd_rn(aa, sar[j]), inter), 1e-7f);
                if (__fdiv_rn(inter, denom) > IOU_T)
                    atomicOr(&tm[(j >> 6) * KCAND + i], 1ull << (j & 63));
            }
        }
    }
    __syncthreads();

    // ========== 6. nonzero-row bitmap ==========
    if (tid < KCAND) {
        u64 o = tm[tid]            | tm[KCAND     + tid] |
                tm[2*KCAND + tid]  | tm[3*KCAND   + tid] |
                tm[4*KCAND + tid]  | tm[5*KCAND   + tid] |
                tm[6*KCAND + tid]  | tm[7*KCAND   + tid];
        unsigned bnz = __ballot_sync(0xffffffffu, o != 0ull);
        if ((tid & 31) == 0) nz32[tid >> 5] = bnz;
    }
    __syncthreads();

    // ========== 7. sparse serial greedy (smem latency) ==========
    if (tid == 0) {
        u64 sup[8] = {0,0,0,0,0,0,0,0};
        u64 nz[8];
        #pragma unroll
        for (int q = 0; q < 8; ++q)
            nz[q] = (u64)nz32[2*q] | ((u64)nz32[2*q + 1] << 32);
        #pragma unroll
        for (int w = 0; w < 8; ++w) {
            u64 x = nz[w] & ~sup[w];
            while (x) {
                int bb = __ffsll((long long)x) - 1;
                int i = (w << 6) + bb;
                #pragma unroll
                for (int q = 0; q < 8; ++q) sup[q] |= tm[q * KCAND + i];
                u64 above = (bb == 63) ? 0ull : (~0ull << (bb + 1));
                x = nz[w] & ~sup[w] & above;
            }
        }
        int nconf = s_nconf;
        int nv = 0;
        #pragma unroll
        for (int w = 0; w < 8; ++w) {
            int lo = nconf - (w << 6);
            u64 conf = (lo >= 64) ? ~0ull : ((lo <= 0) ? 0ull : ((1ull << lo) - 1ull));
            u64 valid = (~sup[w]) & conf;
            if (w == 0) valid |= 1ull;     // index 0: never suppressed, rank 1
            valid32[2*w]     = (unsigned int)valid;
            valid32[2*w + 1] = (unsigned int)(valid >> 32);
            nv += __popcll(valid);
        }
        s_nv = nv;
    }
    __syncthreads();

    // ========== 8. parallel pack (valid asc, then invalid asc) ==========
    if (tid < MAXDET) {
        int nv = s_nv;
        bool isv = tid < nv;
        int r = isv ? tid : tid - nv;
        int k = -1;
        #pragma unroll
        for (int wi = 0; wi < 16; ++wi) {
            unsigned wv = valid32[wi];
            if (!isv) wv = ~wv;
            int c = __popc(wv);
            if (k < 0) {
                if (r < c) k = wi * 32 + __fns(wv, 0, r + 1);
                else       r -= c;
            }
        }
        int gi = topiS[k];
        float b0 = 0.f, b1 = 0.f, b2 = 0.f, b3 = 0.f, sc = 0.f;
        if (isv) {
            const float4* p = (const float4*)(pred + ((size_t)b * NVAL + gi) * 8);
            float4 a = p[0];
            float hw = __fmul_rn(a.z, 0.5f), hh = __fmul_rn(a.w, 0.5f);
            b0 = __fsub_rn(a.x, hw); b1 = __fsub_rn(a.y, hh);
            b2 = __fadd_rn(a.x, hw); b3 = __fadd_rn(a.y, hh);
            sc = scoreS[k];
        }
        const size_t scoresOff = (size_t)BS * MAXDET * 4;
        const size_t clsOff    = scoresOff + (size_t)BS * MAXDET;
        const size_t idsOff    = clsOff    + (size_t)BS * MAXDET;
        const size_t valOff    = idsOff    + (size_t)BS * MAXDET;
        size_t rr = (size_t)b * MAXDET + tid;
        out[rr * 4 + 0] = b0;
        out[rr * 4 + 1] = b1;
        out[rr * 4 + 2] = b2;
        out[rr * 4 + 3] = b3;
        out[scoresOff + rr] = sc;
        out[clsOff + rr] = (float)cidS[k];     // NOT zeroed for pads (ref semantics)
        out[idsOff + rr] = (float)(gi / 3);    // NOT zeroed for pads (ref semantics)
        out[valOff + rr] = isv ? 1.0f : 0.0f;
    }
}

// ---------------------------------------------------------------------------
extern "C" void kernel_launch(void* const* d_in, const int* in_sizes, int n_in,
                              void* d_out, int out_size) {
    (void)in_sizes; (void)n_in; (void)out_size;
    const float* pred = (const float*)d_in[0];
    float* out = (float*)d_out;

    score_kernel<<<dim3(25, BS), 1024>>>(pred);
    cudaFuncSetAttribute(perimage_kernel,
                         cudaFuncAttributeMaxDynamicSharedMemorySize, 106496);
    perimage_kernel<<<BS, 1024, 106496>>>(pred, out);
}